// round 9
// baseline (speedup 1.0000x reference)
#include <cuda_runtime.h>
#include <cuda_bf16.h>
#include <cuda_fp16.h>
#include <cstdint>
#include <math.h>

#define BB 8
#define NN 2048
#define FI 128
#define FO 64
#define KT 64
#define TI 64
#define NCHUNK (NN / KT)

// ---------------- scratch (static device arrays: allocation-free) ----------
__device__ __half g_Wh_h[(size_t)BB * NN * FO];  // [row][f] 2MB, fp16
__device__ float4 g_srow[BB * NN];   // (-s1, exp(s1), exp(0.2 s1), 0)
__device__ float4 g_scol[BB * NN];   // (s2, exp(s2), exp(0.2 s2), 0)

// ---------------- helpers ---------------------------------------------------
__device__ __forceinline__ uint32_t smem_u32(const void* p) {
    uint32_t a;
    asm("{ .reg .u64 t; cvta.to.shared.u64 t, %1; cvt.u32.u64 %0, t; }" : "=r"(a) : "l"(p));
    return a;
}

__device__ __forceinline__ void mma16816(float* c, uint32_t a0, uint32_t a1,
                                         uint32_t a2, uint32_t a3,
                                         uint32_t b0, uint32_t b1) {
    asm volatile("mma.sync.aligned.m16n8k16.row.col.f32.f16.f16.f32 "
                 "{%0,%1,%2,%3}, {%4,%5,%6,%7}, {%8,%9}, {%0,%1,%2,%3};"
                 : "+f"(c[0]), "+f"(c[1]), "+f"(c[2]), "+f"(c[3])
                 : "r"(a0), "r"(a1), "r"(a2), "r"(a3), "r"(b0), "r"(b1));
}

__device__ __forceinline__ void ldsm4t(uint32_t* r, uint32_t addr) {
    asm volatile("ldmatrix.sync.aligned.m8n8.x4.trans.shared.b16 {%0,%1,%2,%3}, [%4];"
                 : "=r"(r[0]), "=r"(r[1]), "=r"(r[2]), "=r"(r[3]) : "r"(addr));
}

__device__ __forceinline__ void cpasync16(uint32_t dst, const void* src) {
    asm volatile("cp.async.ca.shared.global [%0], [%1], 16;" :: "r"(dst), "l"(src));
}

__device__ __forceinline__ int2 lds64(uint32_t addr) {
    int2 v;
    asm volatile("ld.shared.v2.u32 {%0, %1}, [%2];" : "=r"(v.x), "=r"(v.y) : "r"(addr));
    return v;
}

__device__ __forceinline__ uint32_t packhf2(float x, float y) {
    __half2 v = __float22half2_rn(make_float2(x, y));
    return *(uint32_t*)&v;
}

__device__ __forceinline__ float f4c(const float4& v, int k) {
    return k == 0 ? v.x : (k == 1 ? v.y : (k == 2 ? v.z : v.w));
}

// p = adj ? (s1+s2>0 ? E1*E2 : F1*F2) : 0
// rp = (-s1, E1, F1, _)    sc = (s2, E2, F2, _)
__device__ __forceinline__ float pval(const float4& rp, const float4& sc, int adjv) {
    const bool gt = sc.x > rp.x;
    const float e1 = gt ? rp.y : rp.z;
    const float e2 = gt ? sc.y : sc.z;
    return adjv ? e1 * e2 : 0.f;
}

// ---------------------------------------------------------------------------
// Kernel 1: Wh = h @ W ; emits g_Wh_h ([row][f], fp16) + per-node attention
// tables g_srow / g_scol. 64 rows/block (256 blocks), thread tile 2r x 8f.
// ---------------------------------------------------------------------------
__global__ void __launch_bounds__(256, 2) wh_kernel(const float* __restrict__ h,
                                                    const float* __restrict__ W,
                                                    const float* __restrict__ a) {
    extern __shared__ __align__(16) unsigned char smem_raw[];
    float4* sh4 = (float4*)smem_raw;                     // 64 x 128 f32 = 32KB
    float4* sW4 = (float4*)(smem_raw + 32768);           // 128 x 64 f32 = 32KB

    const int tid  = threadIdx.x;
    const int row0 = blockIdx.x * 64;

    const float4* hsrc = (const float4*)(h + (size_t)row0 * FI);
    #pragma unroll 2
    for (int i = tid; i < 64 * FI / 4; i += 256) sh4[i] = hsrc[i];
    const float4* wsrc = (const float4*)W;
    #pragma unroll 2
    for (int i = tid; i < FI * FO / 4; i += 256) sW4[i] = wsrc[i];
    __syncthreads();

    const int fg   = tid & 7;    // feature group: f0 = fg*8
    const int rowg = tid >> 3;   // 0..31: rows rowg*2, rowg*2+1

    float acc[2][8];
    #pragma unroll
    for (int r = 0; r < 2; ++r)
        #pragma unroll
        for (int c = 0; c < 8; ++c) acc[r][c] = 0.f;

    #pragma unroll 4
    for (int k4 = 0; k4 < FI / 4; ++k4) {
        float4 hv[2];
        #pragma unroll
        for (int r = 0; r < 2; ++r) hv[r] = sh4[(rowg * 2 + r) * (FI / 4) + k4];
        #pragma unroll
        for (int kk = 0; kk < 4; ++kk) {
            const float4 wa = sW4[(k4 * 4 + kk) * 16 + fg * 2];
            const float4 wb = sW4[(k4 * 4 + kk) * 16 + fg * 2 + 1];
            #pragma unroll
            for (int r = 0; r < 2; ++r) {
                const float hk = f4c(hv[r], kk);
                acc[r][0] = fmaf(hk, wa.x, acc[r][0]);
                acc[r][1] = fmaf(hk, wa.y, acc[r][1]);
                acc[r][2] = fmaf(hk, wa.z, acc[r][2]);
                acc[r][3] = fmaf(hk, wa.w, acc[r][3]);
                acc[r][4] = fmaf(hk, wb.x, acc[r][4]);
                acc[r][5] = fmaf(hk, wb.y, acc[r][5]);
                acc[r][6] = fmaf(hk, wb.z, acc[r][6]);
                acc[r][7] = fmaf(hk, wb.w, acc[r][7]);
            }
        }
    }

    // ---- s1/s2 partials over this thread's 8 features, reduce over fg lanes
    const float4* a4 = (const float4*)a;
    const float4 a1a = a4[fg * 2], a1b = a4[fg * 2 + 1];
    const float4 a2a = a4[16 + fg * 2], a2b = a4[16 + fg * 2 + 1];
    float s1p[2], s2p[2];
    #pragma unroll
    for (int r = 0; r < 2; ++r) {
        s1p[r] = acc[r][0] * a1a.x + acc[r][1] * a1a.y + acc[r][2] * a1a.z + acc[r][3] * a1a.w
               + acc[r][4] * a1b.x + acc[r][5] * a1b.y + acc[r][6] * a1b.z + acc[r][7] * a1b.w;
        s2p[r] = acc[r][0] * a2a.x + acc[r][1] * a2a.y + acc[r][2] * a2a.z + acc[r][3] * a2a.w
               + acc[r][4] * a2b.x + acc[r][5] * a2b.y + acc[r][6] * a2b.z + acc[r][7] * a2b.w;
    }
    #pragma unroll
    for (int off = 1; off < 8; off <<= 1)
        #pragma unroll
        for (int r = 0; r < 2; ++r) {
            s1p[r] += __shfl_xor_sync(0xffffffffu, s1p[r], off);
            s2p[r] += __shfl_xor_sync(0xffffffffu, s2p[r], off);
        }
    if (fg == 0) {
        #pragma unroll
        for (int r = 0; r < 2; ++r) {
            const int row = row0 + rowg * 2 + r;
            const float s1 = s1p[r], s2 = s2p[r];
            g_srow[row] = make_float4(-s1, __expf(s1), __expf(0.2f * s1), 0.f);
            g_scol[row] = make_float4(s2, __expf(s2), __expf(0.2f * s2), 0.f);
        }
    }

    // ---- fp16 plane, natural [row][f] layout
    #pragma unroll
    for (int r = 0; r < 2; ++r) {
        const int row = row0 + rowg * 2 + r;
        uint32_t hw[4];
        #pragma unroll
        for (int cp = 0; cp < 4; ++cp)
            hw[cp] = packhf2(acc[r][cp * 2], acc[r][cp * 2 + 1]);
        *(uint4*)(g_Wh_h + (size_t)row * FO + fg * 8) = make_uint4(hw[0], hw[1], hw[2], hw[3]);
    }
}

// ---------------------------------------------------------------------------
// Kernel 2: fused GAT attention via mma.sync fp16, K-split warps, and a
// cp.async double-buffer pipeline for BOTH Wh tiles and adj tiles.
// CTA: 64 i-rows x 64 f. Warp pair (p, p+4): rows p*16..+15; warp p handles
// k-slices 0-1, warp p+4 k-slices 2-3; fp32 partial accs merged at epilogue.
// ---------------------------------------------------------------------------
#define SB_STRIDE 144            // 64 fp16 + 16B pad
#define SB_PLANE  (64 * SB_STRIDE)          // 9216
#define ADJ_STRIDE 272           // (64+4) ints, 16B aligned, bank-spread
#define ADJ_TILE  (64 * ADJ_STRIDE)         // 17408
#define OFF_SB    32768
#define OFF_ADJ   (OFF_SB + 2 * SB_PLANE)   // 51200
#define OFF_SROW  (OFF_ADJ + 2 * ADJ_TILE)  // 86016
#define ACC_STRIDE 68            // padded f32 stride for acc exchange
#define GAT_SMEM  (OFF_SROW + 512)          // 86528

__device__ __forceinline__ void stage_chunk(uint32_t sb, int buf, int rowbase,
                                            const int* __restrict__ adjbase, int j0,
                                            int tid) {
    // Wh tile: 64 rows x 64 fp16 (8 KB)
    #pragma unroll
    for (int q = 0; q < 2; ++q) {
        const int id  = tid + q * 256;     // 0..511
        const int row = id >> 3;
        const int c16 = id & 7;
        const __half* src = g_Wh_h + (size_t)(rowbase + row) * FO + c16 * 8;
        const uint32_t dst = sb + OFF_SB - OFF_SB + buf * SB_PLANE + row * SB_STRIDE + c16 * 16;
        cpasync16(dst, src);
    }
    // adj tile: 64 rows x 64 int32 (16 KB), padded stride
    const uint32_t abase = sb + (OFF_ADJ - OFF_SB) + buf * ADJ_TILE;
    #pragma unroll
    for (int q = 0; q < 4; ++q) {
        const int id  = tid + q * 256;     // 0..1023
        const int row = id >> 4;
        const int c16 = id & 15;
        const int* src = adjbase + (size_t)row * NN + j0 + c16 * 4;
        cpasync16(abase + row * ADJ_STRIDE + c16 * 16, src);
    }
}

__global__ void __launch_bounds__(256, 2) gat_kernel(const int* __restrict__ adj,
                                                     float* __restrict__ out) {
    extern __shared__ __align__(16) unsigned char smem_raw[];
    float4* scol = (float4*)smem_raw;                       // 32KB
    float*  srow = (float*)(smem_raw + OFF_SROW);           // [2][64]
    float*  accbuf = (float*)(smem_raw + OFF_SB);           // reuses Wh staging
    const uint32_t sb = smem_u32(smem_raw) + OFF_SB;        // staging base
    const uint32_t sadj = smem_u32(smem_raw) + OFF_ADJ;

    const int tid  = threadIdx.x;
    const int lane = tid & 31;
    const int wid  = tid >> 5;
    const int b    = blockIdx.y;
    const int i0   = blockIdx.x * TI;

    const int mb    = (wid & 3) * 16;   // warp row base (local, 0..48)
    const int khalf = wid >> 2;         // 0: k-slices 0-1, 1: k-slices 2-3
    const int lrl = mb + (lane >> 2);   // local row (lo)
    const int lrh = lrl + 8;
    const int qc  = (lane & 3) * 2;     // k-pair base within 16

    // preload scol for batch b (f32 tables: exact P)
    {
        const float4* src = (const float4*)(g_scol + b * NN);
        #pragma unroll 2
        for (int i = tid; i < NN; i += 256) scol[i] = src[i];
    }

    const float4 rp_lo = g_srow[b * NN + i0 + lrl];
    const float4 rp_hi = g_srow[b * NN + i0 + lrh];
    const int* adjbase = adj + ((size_t)b * NN + i0) * NN;

    stage_chunk(sb, 0, b * NN, adjbase, 0, tid);
    asm volatile("cp.async.commit_group;" ::: "memory");
    __syncthreads();   // scol visible

    float acc[8][4];
    #pragma unroll
    for (int nt = 0; nt < 8; ++nt)
        #pragma unroll
        for (int k = 0; k < 4; ++k) acc[nt][k] = 0.f;
    float rsum_lo = 0.f, rsum_hi = 0.f;

    const int lrow = (lane & 7) + (lane & 8);       // ldmatrix row 0..15
    const int lcol = (lane >> 4) << 3;              // 0 or 8

    #pragma unroll 1
    for (int t = 0; t < NCHUNK; ++t) {
        if (t + 1 < NCHUNK) {
            stage_chunk(sb, (t + 1) & 1, b * NN + (t + 1) * KT, adjbase, (t + 1) * KT, tid);
            asm volatile("cp.async.commit_group;" ::: "memory");
            asm volatile("cp.async.wait_group 1;" ::: "memory");
        } else {
            asm volatile("cp.async.wait_group 0;" ::: "memory");
        }
        __syncthreads();   // chunk t landed everywhere

        const uint32_t bufh  = sb + (t & 1) * SB_PLANE;
        const uint32_t abuf  = sadj + (t & 1) * ADJ_TILE;

        #pragma unroll
        for (int kt2 = 0; kt2 < 2; ++kt2) {
            const int ktg = khalf * 2 + kt2;          // this warp's k-slice
            const int jl  = ktg * 16 + qc;            // local j within chunk
            const float4 sc0 = scol[t * KT + jl];
            const float4 sc1 = scol[t * KT + jl + 1];
            const float4 sc8 = scol[t * KT + jl + 8];
            const float4 sc9 = scol[t * KT + jl + 9];
            const uint32_t al_lo = abuf + lrl * ADJ_STRIDE + jl * 4;
            const uint32_t al_hi = abuf + lrh * ADJ_STRIDE + jl * 4;
            const int2 al0 = lds64(al_lo);
            const int2 al8 = lds64(al_lo + 32);
            const int2 ah0 = lds64(al_hi);
            const int2 ah8 = lds64(al_hi + 32);

            const float pl0 = pval(rp_lo, sc0, al0.x);
            const float pl1 = pval(rp_lo, sc1, al0.y);
            const float pl8 = pval(rp_lo, sc8, al8.x);
            const float pl9 = pval(rp_lo, sc9, al8.y);
            const float ph0 = pval(rp_hi, sc0, ah0.x);
            const float ph1 = pval(rp_hi, sc1, ah0.y);
            const float ph8 = pval(rp_hi, sc8, ah8.x);
            const float ph9 = pval(rp_hi, sc9, ah8.y);

            rsum_lo += (pl0 + pl1) + (pl8 + pl9);
            rsum_hi += (ph0 + ph1) + (ph8 + ph9);

            const uint32_t a0 = packhf2(pl0, pl1);
            const uint32_t a1 = packhf2(ph0, ph1);
            const uint32_t a2 = packhf2(pl8, pl9);
            const uint32_t a3 = packhf2(ph8, ph9);

            // all 64 cols, 16 at a time (keeps B-reg pressure at 4)
            const uint32_t rowoff = (uint32_t)(ktg * 16 + lrow) * SB_STRIDE + lcol * 2;
            #pragma unroll
            for (int ci = 0; ci < 4; ++ci) {
                uint32_t bt[4];
                ldsm4t(bt, bufh + rowoff + ci * 32);
                mma16816(acc[ci * 2 + 0], a0, a1, a2, a3, bt[0], bt[1]);
                mma16816(acc[ci * 2 + 1], a0, a1, a2, a3, bt[2], bt[3]);
            }
        }
        __syncthreads();   // all reads of buffers t done before re-staging
    }

    // ---- rowsum partials (per khalf) -> smem
    rsum_lo += __shfl_xor_sync(0xffffffffu, rsum_lo, 1);
    rsum_lo += __shfl_xor_sync(0xffffffffu, rsum_lo, 2);
    rsum_hi += __shfl_xor_sync(0xffffffffu, rsum_hi, 1);
    rsum_hi += __shfl_xor_sync(0xffffffffu, rsum_hi, 2);
    if ((lane & 3) == 0) {
        srow[khalf * 64 + lrl] = rsum_lo;
        srow[khalf * 64 + lrh] = rsum_hi;
    }

    // ---- acc merge: khalf=1 publishes partials (staging area reusable now)
    if (khalf) {
        #pragma unroll
        for (int nt = 0; nt < 8; ++nt) {
            *(float2*)(accbuf + lrl * ACC_STRIDE + nt * 8 + qc) =
                make_float2(acc[nt][0], acc[nt][1]);
            *(float2*)(accbuf + lrh * ACC_STRIDE + nt * 8 + qc) =
                make_float2(acc[nt][2], acc[nt][3]);
        }
    }
    __syncthreads();

    if (!khalf) {
        const float invl = 1.0f / (srow[lrl] + srow[64 + lrl]);
        const float invh = 1.0f / (srow[lrh] + srow[64 + lrh]);
        float* outl = out + (size_t)(b * NN + i0 + lrl) * FO;
        float* outh = out + (size_t)(b * NN + i0 + lrh) * FO;
        #pragma unroll
        for (int nt = 0; nt < 8; ++nt) {
            const int cb = nt * 8 + qc;
            const float2 tl = *(const float2*)(accbuf + lrl * ACC_STRIDE + cb);
            const float2 th = *(const float2*)(accbuf + lrh * ACC_STRIDE + cb);
            float2 o;
            float v;
            v = (acc[nt][0] + tl.x) * invl; o.x = (v > 0.f) ? v : expm1f(v);
            v = (acc[nt][1] + tl.y) * invl; o.y = (v > 0.f) ? v : expm1f(v);
            *(float2*)(outl + cb) = o;
            v = (acc[nt][2] + th.x) * invh; o.x = (v > 0.f) ? v : expm1f(v);
            v = (acc[nt][3] + th.y) * invh; o.y = (v > 0.f) ? v : expm1f(v);
            *(float2*)(outh + cb) = o;
        }
    }
}

// ---------------------------------------------------------------------------
extern "C" void kernel_launch(void* const* d_in, const int* in_sizes, int n_in,
                              void* d_out, int out_size) {
    const float* h   = (const float*)d_in[0];   // [8,2048,128] f32
    const float* W   = (const float*)d_in[1];   // [128,64] f32
    const float* a   = (const float*)d_in[2];   // [128,1] f32
    const int*   adj = (const int*)d_in[3];     // [8,2048,2048] i32
    float* out = (float*)d_out;                 // [8,2048,64] f32

    cudaFuncSetAttribute(wh_kernel, cudaFuncAttributeMaxDynamicSharedMemorySize, 65536);
    cudaFuncSetAttribute(gat_kernel, cudaFuncAttributeMaxDynamicSharedMemorySize, GAT_SMEM);

    wh_kernel<<<BB * NN / 64, 256, 65536>>>(h, W, a);
    dim3 grid(NN / TI, BB);
    gat_kernel<<<grid, 256, GAT_SMEM>>>(adj, out);
}

// round 10
// speedup vs baseline: 1.1176x; 1.1176x over previous
#include <cuda_runtime.h>
#include <cuda_bf16.h>
#include <cuda_fp16.h>
#include <cstdint>
#include <math.h>

#define BB 8
#define NN 2048
#define FI 128
#define FO 64
#define KT 64
#define TI 64
#define NCHUNK (NN / KT)

// ---------------- scratch (static device arrays: allocation-free) ----------
__device__ __half g_Wh_h[(size_t)BB * NN * FO];  // [row][f] 2MB, fp16
__device__ float4 g_srow[BB * NN];   // (-s1, exp(s1), exp(0.2 s1), 0)
__device__ float4 g_scol[BB * NN];   // (s2, exp(s2), exp(0.2 s2), 0)

// ---------------- helpers ---------------------------------------------------
__device__ __forceinline__ uint32_t smem_u32(const void* p) {
    uint32_t a;
    asm("{ .reg .u64 t; cvta.to.shared.u64 t, %1; cvt.u32.u64 %0, t; }" : "=r"(a) : "l"(p));
    return a;
}

__device__ __forceinline__ void mma16816(float* c, uint32_t a0, uint32_t a1,
                                         uint32_t a2, uint32_t a3,
                                         uint32_t b0, uint32_t b1) {
    asm volatile("mma.sync.aligned.m16n8k16.row.col.f32.f16.f16.f32 "
                 "{%0,%1,%2,%3}, {%4,%5,%6,%7}, {%8,%9}, {%0,%1,%2,%3};"
                 : "+f"(c[0]), "+f"(c[1]), "+f"(c[2]), "+f"(c[3])
                 : "r"(a0), "r"(a1), "r"(a2), "r"(a3), "r"(b0), "r"(b1));
}

__device__ __forceinline__ void ldsm4t(uint32_t* r, uint32_t addr) {
    asm volatile("ldmatrix.sync.aligned.m8n8.x4.trans.shared.b16 {%0,%1,%2,%3}, [%4];"
                 : "=r"(r[0]), "=r"(r[1]), "=r"(r[2]), "=r"(r[3]) : "r"(addr));
}

__device__ __forceinline__ void cpasync16(uint32_t dst, const void* src) {
    asm volatile("cp.async.ca.shared.global [%0], [%1], 16;" :: "r"(dst), "l"(src));
}

__device__ __forceinline__ void cpasync16cg(uint32_t dst, const void* src) {
    asm volatile("cp.async.cg.shared.global [%0], [%1], 16;" :: "r"(dst), "l"(src));
}

__device__ __forceinline__ int2 lds64(uint32_t addr) {
    int2 v;
    asm volatile("ld.shared.v2.u32 {%0, %1}, [%2];" : "=r"(v.x), "=r"(v.y) : "r"(addr));
    return v;
}

__device__ __forceinline__ uint32_t packhf2(float x, float y) {
    __half2 v = __float22half2_rn(make_float2(x, y));
    return *(uint32_t*)&v;
}

__device__ __forceinline__ float f4c(const float4& v, int k) {
    return k == 0 ? v.x : (k == 1 ? v.y : (k == 2 ? v.z : v.w));
}

// p = adj ? (s1+s2>0 ? E1*E2 : F1*F2) : 0
// rp = (-s1, E1, F1, _)    sc = (s2, E2, F2, _)
__device__ __forceinline__ float pval(const float4& rp, const float4& sc, int adjv) {
    const bool gt = sc.x > rp.x;
    const float e1 = gt ? rp.y : rp.z;
    const float e2 = gt ? sc.y : sc.z;
    return adjv ? e1 * e2 : 0.f;
}

// ---------------------------------------------------------------------------
// Kernel 1: Wh = h @ W ; emits g_Wh_h ([row][f], fp16) + per-node attention
// tables g_srow / g_scol. 128 rows/block, thread tile 4 rows x 8 features.
// ---------------------------------------------------------------------------
__global__ void __launch_bounds__(256, 2) wh_kernel(const float* __restrict__ h,
                                                    const float* __restrict__ W,
                                                    const float* __restrict__ a) {
    extern __shared__ __align__(16) unsigned char smem_raw[];
    float4* sh4 = (float4*)smem_raw;                     // 128 x 128 f32 = 64KB
    float4* sW4 = (float4*)(smem_raw + 65536);           // 128 x 64 f32 = 32KB

    const int tid  = threadIdx.x;
    const int row0 = blockIdx.x * 128;

    const float4* hsrc = (const float4*)(h + (size_t)row0 * FI);
    #pragma unroll 4
    for (int i = tid; i < 128 * FI / 4; i += 256) sh4[i] = hsrc[i];
    const float4* wsrc = (const float4*)W;
    #pragma unroll 2
    for (int i = tid; i < FI * FO / 4; i += 256) sW4[i] = wsrc[i];
    __syncthreads();

    const int fg   = tid & 7;    // feature group: f0 = fg*8
    const int rowg = tid >> 3;   // 0..31: rows rowg*4 .. +3

    float acc[4][8];
    #pragma unroll
    for (int r = 0; r < 4; ++r)
        #pragma unroll
        for (int c = 0; c < 8; ++c) acc[r][c] = 0.f;

    #pragma unroll 2
    for (int k4 = 0; k4 < FI / 4; ++k4) {
        float4 hv[4];
        #pragma unroll
        for (int r = 0; r < 4; ++r) hv[r] = sh4[(rowg * 4 + r) * (FI / 4) + k4];
        #pragma unroll
        for (int kk = 0; kk < 4; ++kk) {
            const float4 wa = sW4[(k4 * 4 + kk) * 16 + fg * 2];
            const float4 wb = sW4[(k4 * 4 + kk) * 16 + fg * 2 + 1];
            #pragma unroll
            for (int r = 0; r < 4; ++r) {
                const float hk = f4c(hv[r], kk);
                acc[r][0] = fmaf(hk, wa.x, acc[r][0]);
                acc[r][1] = fmaf(hk, wa.y, acc[r][1]);
                acc[r][2] = fmaf(hk, wa.z, acc[r][2]);
                acc[r][3] = fmaf(hk, wa.w, acc[r][3]);
                acc[r][4] = fmaf(hk, wb.x, acc[r][4]);
                acc[r][5] = fmaf(hk, wb.y, acc[r][5]);
                acc[r][6] = fmaf(hk, wb.z, acc[r][6]);
                acc[r][7] = fmaf(hk, wb.w, acc[r][7]);
            }
        }
    }

    // ---- s1/s2 partials over this thread's 8 features, reduce over fg lanes
    const float4* a4 = (const float4*)a;
    const float4 a1a = a4[fg * 2], a1b = a4[fg * 2 + 1];
    const float4 a2a = a4[16 + fg * 2], a2b = a4[16 + fg * 2 + 1];
    float s1p[4], s2p[4];
    #pragma unroll
    for (int r = 0; r < 4; ++r) {
        s1p[r] = acc[r][0] * a1a.x + acc[r][1] * a1a.y + acc[r][2] * a1a.z + acc[r][3] * a1a.w
               + acc[r][4] * a1b.x + acc[r][5] * a1b.y + acc[r][6] * a1b.z + acc[r][7] * a1b.w;
        s2p[r] = acc[r][0] * a2a.x + acc[r][1] * a2a.y + acc[r][2] * a2a.z + acc[r][3] * a2a.w
               + acc[r][4] * a2b.x + acc[r][5] * a2b.y + acc[r][6] * a2b.z + acc[r][7] * a2b.w;
    }
    #pragma unroll
    for (int off = 1; off < 8; off <<= 1)
        #pragma unroll
        for (int r = 0; r < 4; ++r) {
            s1p[r] += __shfl_xor_sync(0xffffffffu, s1p[r], off);
            s2p[r] += __shfl_xor_sync(0xffffffffu, s2p[r], off);
        }
    if (fg == 0) {
        #pragma unroll
        for (int r = 0; r < 4; ++r) {
            const int row = row0 + rowg * 4 + r;
            const float s1 = s1p[r], s2 = s2p[r];
            g_srow[row] = make_float4(-s1, __expf(s1), __expf(0.2f * s1), 0.f);
            g_scol[row] = make_float4(s2, __expf(s2), __expf(0.2f * s2), 0.f);
        }
    }

    // ---- fp16 plane, natural [row][f] layout
    #pragma unroll
    for (int r = 0; r < 4; ++r) {
        const int row = row0 + rowg * 4 + r;
        uint32_t hw[4];
        #pragma unroll
        for (int cp = 0; cp < 4; ++cp)
            hw[cp] = packhf2(acc[r][cp * 2], acc[r][cp * 2 + 1]);
        *(uint4*)(g_Wh_h + (size_t)row * FO + fg * 8) = make_uint4(hw[0], hw[1], hw[2], hw[3]);
    }
}

// ---------------------------------------------------------------------------
// Kernel 2: fused GAT attention via mma.sync fp16, K-split warps, and a
// 3-stage cp.async pipeline for BOTH Wh tiles and adj tiles.
// CTA: 64 i-rows x 64 f. Warp pair (p, p+4): rows p*16..+15; warp p handles
// k-slices 0-1, warp p+4 k-slices 2-3; fp32 partial accs merged at epilogue.
// ---------------------------------------------------------------------------
#define SB_STRIDE 144            // 64 fp16 + 16B pad
#define SB_PLANE  (64 * SB_STRIDE)          // 9216
#define ADJ_STRIDE 272           // (64+4) ints, 16B aligned, bank-spread
#define ADJ_TILE  (64 * ADJ_STRIDE)         // 17408
#define NSTAGE 3
#define OFF_SB    32768
#define OFF_ADJ   (OFF_SB + NSTAGE * SB_PLANE)   // 60416
#define GAT_SMEM  (OFF_ADJ + NSTAGE * ADJ_TILE)  // 112640
#define ACC_STRIDE 68            // padded f32 stride for acc exchange
#define OFF_SROW  (OFF_SB + 64 * ACC_STRIDE * 4) // 50176: after accbuf, inside staging

__device__ __forceinline__ void stage_chunk(uint32_t swh, uint32_t sadj, int buf,
                                            int rowbase, const int* __restrict__ adjbase,
                                            int j0, int tid) {
    // Wh tile: 64 rows x 64 fp16 (8 KB), L1-cached (cross-CTA reuse)
    const uint32_t wbase = swh + buf * SB_PLANE;
    #pragma unroll
    for (int q = 0; q < 2; ++q) {
        const int id  = tid + q * 256;     // 0..511
        const int row = id >> 3;
        const int c16 = id & 7;
        const __half* src = g_Wh_h + (size_t)(rowbase + row) * FO + c16 * 8;
        cpasync16(wbase + row * SB_STRIDE + c16 * 16, src);
    }
    // adj tile: 64 rows x 64 int32 (16 KB), L1-bypass (single use chip-wide)
    const uint32_t abase = sadj + buf * ADJ_TILE;
    #pragma unroll
    for (int q = 0; q < 4; ++q) {
        const int id  = tid + q * 256;     // 0..1023
        const int row = id >> 4;
        const int c16 = id & 15;
        const int* src = adjbase + (size_t)row * NN + j0 + c16 * 4;
        cpasync16cg(abase + row * ADJ_STRIDE + c16 * 16, src);
    }
}

__global__ void __launch_bounds__(256, 2) gat_kernel(const int* __restrict__ adj,
                                                     float* __restrict__ out) {
    extern __shared__ __align__(16) unsigned char smem_raw[];
    float4* scol = (float4*)smem_raw;                       // 32KB
    float*  srow = (float*)(smem_raw + OFF_SROW);           // [2][64], inside staging
    float*  accbuf = (float*)(smem_raw + OFF_SB);           // reuses Wh staging
    const uint32_t swh  = smem_u32(smem_raw) + OFF_SB;
    const uint32_t sadj = smem_u32(smem_raw) + OFF_ADJ;

    const int tid  = threadIdx.x;
    const int lane = tid & 31;
    const int wid  = tid >> 5;
    const int b    = blockIdx.y;
    const int i0   = blockIdx.x * TI;

    const int mb    = (wid & 3) * 16;   // warp row base (local, 0..48)
    const int khalf = wid >> 2;         // 0: k-slices 0-1, 1: k-slices 2-3
    const int lrl = mb + (lane >> 2);   // local row (lo)
    const int lrh = lrl + 8;
    const int qc  = (lane & 3) * 2;     // k-pair base within 16

    // preload scol for batch b (f32 tables: exact P)
    {
        const float4* src = (const float4*)(g_scol + b * NN);
        #pragma unroll 2
        for (int i = tid; i < NN; i += 256) scol[i] = src[i];
    }

    const float4 rp_lo = g_srow[b * NN + i0 + lrl];
    const float4 rp_hi = g_srow[b * NN + i0 + lrh];
    const int* adjbase = adj + ((size_t)b * NN + i0) * NN;

    stage_chunk(swh, sadj, 0, b * NN, adjbase, 0, tid);
    asm volatile("cp.async.commit_group;" ::: "memory");
    stage_chunk(swh, sadj, 1, b * NN + KT, adjbase, KT, tid);
    asm volatile("cp.async.commit_group;" ::: "memory");
    __syncthreads();   // scol visible

    float acc[8][4];
    #pragma unroll
    for (int nt = 0; nt < 8; ++nt)
        #pragma unroll
        for (int k = 0; k < 4; ++k) acc[nt][k] = 0.f;
    float rsum_lo = 0.f, rsum_hi = 0.f;

    const int lrow = (lane & 7) + (lane & 8);       // ldmatrix row 0..15
    const int lcol = (lane >> 4) << 3;              // 0 or 8

    #pragma unroll 1
    for (int t = 0; t < NCHUNK; ++t) {
        if (t + 2 < NCHUNK) {
            stage_chunk(swh, sadj, (t + 2) % NSTAGE, b * NN + (t + 2) * KT,
                        adjbase, (t + 2) * KT, tid);
            asm volatile("cp.async.commit_group;" ::: "memory");
            asm volatile("cp.async.wait_group 2;" ::: "memory");
        } else if (t + 1 < NCHUNK) {
            asm volatile("cp.async.wait_group 1;" ::: "memory");
        } else {
            asm volatile("cp.async.wait_group 0;" ::: "memory");
        }
        __syncthreads();   // chunk t landed everywhere

        const uint32_t bufh = swh  + (t % NSTAGE) * SB_PLANE;
        const uint32_t abuf = sadj + (t % NSTAGE) * ADJ_TILE;

        #pragma unroll
        for (int kt2 = 0; kt2 < 2; ++kt2) {
            const int ktg = khalf * 2 + kt2;          // this warp's k-slice
            const int jl  = ktg * 16 + qc;            // local j within chunk
            const float4 sc0 = scol[t * KT + jl];
            const float4 sc1 = scol[t * KT + jl + 1];
            const float4 sc8 = scol[t * KT + jl + 8];
            const float4 sc9 = scol[t * KT + jl + 9];
            const uint32_t al_lo = abuf + lrl * ADJ_STRIDE + jl * 4;
            const uint32_t al_hi = abuf + lrh * ADJ_STRIDE + jl * 4;
            const int2 al0 = lds64(al_lo);
            const int2 al8 = lds64(al_lo + 32);
            const int2 ah0 = lds64(al_hi);
            const int2 ah8 = lds64(al_hi + 32);

            const float pl0 = pval(rp_lo, sc0, al0.x);
            const float pl1 = pval(rp_lo, sc1, al0.y);
            const float pl8 = pval(rp_lo, sc8, al8.x);
            const float pl9 = pval(rp_lo, sc9, al8.y);
            const float ph0 = pval(rp_hi, sc0, ah0.x);
            const float ph1 = pval(rp_hi, sc1, ah0.y);
            const float ph8 = pval(rp_hi, sc8, ah8.x);
            const float ph9 = pval(rp_hi, sc9, ah8.y);

            rsum_lo += (pl0 + pl1) + (pl8 + pl9);
            rsum_hi += (ph0 + ph1) + (ph8 + ph9);

            const uint32_t a0 = packhf2(pl0, pl1);
            const uint32_t a1 = packhf2(ph0, ph1);
            const uint32_t a2 = packhf2(pl8, pl9);
            const uint32_t a3 = packhf2(ph8, ph9);

            // all 64 cols, 16 at a time (keeps B-reg pressure at 4)
            const uint32_t rowoff = (uint32_t)(ktg * 16 + lrow) * SB_STRIDE + lcol * 2;
            #pragma unroll
            for (int ci = 0; ci < 4; ++ci) {
                uint32_t bt[4];
                ldsm4t(bt, bufh + rowoff + ci * 32);
                mma16816(acc[ci * 2 + 0], a0, a1, a2, a3, bt[0], bt[1]);
                mma16816(acc[ci * 2 + 1], a0, a1, a2, a3, bt[2], bt[3]);
            }
        }
        __syncthreads();   // all reads of buffers t done before re-staging
    }

    // ---- rowsum partials (per khalf) -> smem (staging region is free now)
    rsum_lo += __shfl_xor_sync(0xffffffffu, rsum_lo, 1);
    rsum_lo += __shfl_xor_sync(0xffffffffu, rsum_lo, 2);
    rsum_hi += __shfl_xor_sync(0xffffffffu, rsum_hi, 1);
    rsum_hi += __shfl_xor_sync(0xffffffffu, rsum_hi, 2);
    if ((lane & 3) == 0) {
        srow[khalf * 64 + lrl] = rsum_lo;
        srow[khalf * 64 + lrh] = rsum_hi;
    }

    // ---- acc merge: khalf=1 publishes partials
    if (khalf) {
        #pragma unroll
        for (int nt = 0; nt < 8; ++nt) {
            *(float2*)(accbuf + lrl * ACC_STRIDE + nt * 8 + qc) =
                make_float2(acc[nt][0], acc[nt][1]);
            *(float2*)(accbuf + lrh * ACC_STRIDE + nt * 8 + qc) =
                make_float2(acc[nt][2], acc[nt][3]);
        }
    }
    __syncthreads();

    if (!khalf) {
        const float invl = 1.0f / (srow[lrl] + srow[64 + lrl]);
        const float invh = 1.0f / (srow[lrh] + srow[64 + lrh]);
        float* outl = out + (size_t)(b * NN + i0 + lrl) * FO;
        float* outh = out + (size_t)(b * NN + i0 + lrh) * FO;
        #pragma unroll
        for (int nt = 0; nt < 8; ++nt) {
            const int cb = nt * 8 + qc;
            const float2 tl = *(const float2*)(accbuf + lrl * ACC_STRIDE + cb);
            const float2 th = *(const float2*)(accbuf + lrh * ACC_STRIDE + cb);
            float2 o;
            float v;
            v = (acc[nt][0] + tl.x) * invl; o.x = (v > 0.f) ? v : expm1f(v);
            v = (acc[nt][1] + tl.y) * invl; o.y = (v > 0.f) ? v : expm1f(v);
            *(float2*)(outl + cb) = o;
            v = (acc[nt][2] + th.x) * invh; o.x = (v > 0.f) ? v : expm1f(v);
            v = (acc[nt][3] + th.y) * invh; o.y = (v > 0.f) ? v : expm1f(v);
            *(float2*)(outh + cb) = o;
        }
    }
}

// ---------------------------------------------------------------------------
extern "C" void kernel_launch(void* const* d_in, const int* in_sizes, int n_in,
                              void* d_out, int out_size) {
    const float* h   = (const float*)d_in[0];   // [8,2048,128] f32
    const float* W   = (const float*)d_in[1];   // [128,64] f32
    const float* a   = (const float*)d_in[2];   // [128,1] f32
    const int*   adj = (const int*)d_in[3];     // [8,2048,2048] i32
    float* out = (float*)d_out;                 // [8,2048,64] f32

    cudaFuncSetAttribute(wh_kernel, cudaFuncAttributeMaxDynamicSharedMemorySize, 98304);
    cudaFuncSetAttribute(gat_kernel, cudaFuncAttributeMaxDynamicSharedMemorySize, GAT_SMEM);

    wh_kernel<<<BB * NN / 128, 256, 98304>>>(h, W, a);
    dim3 grid(NN / TI, BB);
    gat_kernel<<<grid, 256, GAT_SMEM>>>(adj, out);
}

// round 11
// speedup vs baseline: 1.1477x; 1.0269x over previous
#include <cuda_runtime.h>
#include <cuda_bf16.h>
#include <cuda_fp16.h>
#include <cstdint>
#include <math.h>

#define BB 8
#define NN 2048
#define FI 128
#define FO 64
#define KT 64
#define TI 64
#define NCHUNK (NN / KT)

// ---------------- scratch (static device arrays: allocation-free) ----------
__device__ __half g_Wh_h[(size_t)BB * NN * FO];     // [row][f] 2MB, fp16
__device__ uint4 g_srowP[BB * NN];       // (h2(-s1,-s1), h2(E1,E1), h2(F1,F1), 0)
__device__ uint4 g_scolP[BB * NN / 2];   // per j-pair: (h2(s2,s2'), h2(E2,E2'), h2(F2,F2'), 0)

// ---------------- helpers ---------------------------------------------------
__device__ __forceinline__ uint32_t smem_u32(const void* p) {
    uint32_t a;
    asm("{ .reg .u64 t; cvta.to.shared.u64 t, %1; cvt.u32.u64 %0, t; }" : "=r"(a) : "l"(p));
    return a;
}

__device__ __forceinline__ void mma16816(float* c, uint32_t a0, uint32_t a1,
                                         uint32_t a2, uint32_t a3,
                                         uint32_t b0, uint32_t b1) {
    asm volatile("mma.sync.aligned.m16n8k16.row.col.f32.f16.f16.f32 "
                 "{%0,%1,%2,%3}, {%4,%5,%6,%7}, {%8,%9}, {%0,%1,%2,%3};"
                 : "+f"(c[0]), "+f"(c[1]), "+f"(c[2]), "+f"(c[3])
                 : "r"(a0), "r"(a1), "r"(a2), "r"(a3), "r"(b0), "r"(b1));
}

__device__ __forceinline__ void ldsm4t(uint32_t* r, uint32_t addr) {
    asm volatile("ldmatrix.sync.aligned.m8n8.x4.trans.shared.b16 {%0,%1,%2,%3}, [%4];"
                 : "=r"(r[0]), "=r"(r[1]), "=r"(r[2]), "=r"(r[3]) : "r"(addr));
}

__device__ __forceinline__ void ldsm2t(uint32_t* r, uint32_t addr) {
    asm volatile("ldmatrix.sync.aligned.m8n8.x2.trans.shared.b16 {%0,%1}, [%2];"
                 : "=r"(r[0]), "=r"(r[1]) : "r"(addr));
}

__device__ __forceinline__ void cpasync16(uint32_t dst, const void* src) {
    asm volatile("cp.async.ca.shared.global [%0], [%1], 16;" :: "r"(dst), "l"(src));
}

__device__ __forceinline__ void cpasync16cg(uint32_t dst, const void* src) {
    asm volatile("cp.async.cg.shared.global [%0], [%1], 16;" :: "r"(dst), "l"(src));
}

__device__ __forceinline__ int2 lds64(uint32_t addr) {
    int2 v;
    asm volatile("ld.shared.v2.u32 {%0, %1}, [%2];" : "=r"(v.x), "=r"(v.y) : "r"(addr));
    return v;
}

__device__ __forceinline__ uint32_t h2u(float x, float y) {
    __half2 v = __float22half2_rn(make_float2(x, y));
    return *(uint32_t*)&v;
}

// per-half-lane 0xFFFF mask where a > b (fp16x2 compare)
__device__ __forceinline__ uint32_t setgt2(uint32_t a, uint32_t b) {
    uint32_t m;
    asm("set.gt.u32.f16x2 %0, %1, %2;" : "=r"(m) : "r"(a), "r"(b));
    return m;
}

__device__ __forceinline__ uint32_t hmul2u(uint32_t a, uint32_t b) {
    uint32_t d;
    asm("mul.f16x2 %0, %1, %2;" : "=r"(d) : "r"(a), "r"(b));
    return d;
}

// bit-select: (x & m) | (y & ~m)   -> single LOP3
__device__ __forceinline__ uint32_t bsel(uint32_t x, uint32_t y, uint32_t m) {
    return (x & m) | (y & ~m);
}

// adj pair (0/1 ints) -> packed halfword masks
__device__ __forceinline__ uint32_t adjmask(int a0, int a1) {
    return (uint32_t)(a0 + (a1 << 16)) * 0xFFFFu;
}

__device__ __forceinline__ float f4c(const float4& v, int k) {
    return k == 0 ? v.x : (k == 1 ? v.y : (k == 2 ? v.z : v.w));
}

// ---------------------------------------------------------------------------
// Kernel 1: Wh = h @ W ; emits g_Wh_h ([row][f], fp16) + packed attention
// tables g_srowP / g_scolP. 128 rows/block, thread tile 4 rows x 8 features.
// ---------------------------------------------------------------------------
__global__ void __launch_bounds__(256, 2) wh_kernel(const float* __restrict__ h,
                                                    const float* __restrict__ W,
                                                    const float* __restrict__ a) {
    extern __shared__ __align__(16) unsigned char smem_raw[];
    float4* sh4 = (float4*)smem_raw;                     // 128 x 128 f32 = 64KB
    float4* sW4 = (float4*)(smem_raw + 65536);           // 128 x 64 f32 = 32KB

    const int tid  = threadIdx.x;
    const int row0 = blockIdx.x * 128;

    const float4* hsrc = (const float4*)(h + (size_t)row0 * FI);
    #pragma unroll 4
    for (int i = tid; i < 128 * FI / 4; i += 256) sh4[i] = hsrc[i];
    const float4* wsrc = (const float4*)W;
    #pragma unroll 2
    for (int i = tid; i < FI * FO / 4; i += 256) sW4[i] = wsrc[i];
    __syncthreads();

    const int fg   = tid & 7;    // feature group: f0 = fg*8
    const int rowg = tid >> 3;   // 0..31: rows rowg*4 .. +3

    float acc[4][8];
    #pragma unroll
    for (int r = 0; r < 4; ++r)
        #pragma unroll
        for (int c = 0; c < 8; ++c) acc[r][c] = 0.f;

    #pragma unroll 2
    for (int k4 = 0; k4 < FI / 4; ++k4) {
        float4 hv[4];
        #pragma unroll
        for (int r = 0; r < 4; ++r) hv[r] = sh4[(rowg * 4 + r) * (FI / 4) + k4];
        #pragma unroll
        for (int kk = 0; kk < 4; ++kk) {
            const float4 wa = sW4[(k4 * 4 + kk) * 16 + fg * 2];
            const float4 wb = sW4[(k4 * 4 + kk) * 16 + fg * 2 + 1];
            #pragma unroll
            for (int r = 0; r < 4; ++r) {
                const float hk = f4c(hv[r], kk);
                acc[r][0] = fmaf(hk, wa.x, acc[r][0]);
                acc[r][1] = fmaf(hk, wa.y, acc[r][1]);
                acc[r][2] = fmaf(hk, wa.z, acc[r][2]);
                acc[r][3] = fmaf(hk, wa.w, acc[r][3]);
                acc[r][4] = fmaf(hk, wb.x, acc[r][4]);
                acc[r][5] = fmaf(hk, wb.y, acc[r][5]);
                acc[r][6] = fmaf(hk, wb.z, acc[r][6]);
                acc[r][7] = fmaf(hk, wb.w, acc[r][7]);
            }
        }
    }

    // ---- s1/s2 partials over this thread's 8 features, reduce over fg lanes
    const float4* a4 = (const float4*)a;
    const float4 a1a = a4[fg * 2], a1b = a4[fg * 2 + 1];
    const float4 a2a = a4[16 + fg * 2], a2b = a4[16 + fg * 2 + 1];
    float s1p[4], s2p[4];
    #pragma unroll
    for (int r = 0; r < 4; ++r) {
        s1p[r] = acc[r][0] * a1a.x + acc[r][1] * a1a.y + acc[r][2] * a1a.z + acc[r][3] * a1a.w
               + acc[r][4] * a1b.x + acc[r][5] * a1b.y + acc[r][6] * a1b.z + acc[r][7] * a1b.w;
        s2p[r] = acc[r][0] * a2a.x + acc[r][1] * a2a.y + acc[r][2] * a2a.z + acc[r][3] * a2a.w
               + acc[r][4] * a2b.x + acc[r][5] * a2b.y + acc[r][6] * a2b.z + acc[r][7] * a2b.w;
    }
    #pragma unroll
    for (int off = 1; off < 8; off <<= 1)
        #pragma unroll
        for (int r = 0; r < 4; ++r) {
            s1p[r] += __shfl_xor_sync(0xffffffffu, s1p[r], off);
            s2p[r] += __shfl_xor_sync(0xffffffffu, s2p[r], off);
        }
    if (fg == 0) {
        float e2v[4], f2v[4];
        const int base = row0 + rowg * 4;
        #pragma unroll
        for (int r = 0; r < 4; ++r) {
            const float s1 = s1p[r], s2 = s2p[r];
            const float e1 = __expf(s1), f1 = __expf(0.2f * s1);
            g_srowP[base + r] = make_uint4(h2u(-s1, -s1), h2u(e1, e1), h2u(f1, f1), 0u);
            e2v[r] = __expf(s2);
            f2v[r] = __expf(0.2f * s2);
        }
        #pragma unroll
        for (int pr = 0; pr < 2; ++pr) {
            g_scolP[(base >> 1) + pr] = make_uint4(
                h2u(s2p[pr * 2], s2p[pr * 2 + 1]),
                h2u(e2v[pr * 2], e2v[pr * 2 + 1]),
                h2u(f2v[pr * 2], f2v[pr * 2 + 1]), 0u);
        }
    }

    // ---- fp16 plane, natural [row][f] layout
    #pragma unroll
    for (int r = 0; r < 4; ++r) {
        const int row = row0 + rowg * 4 + r;
        uint32_t hw[4];
        #pragma unroll
        for (int cp = 0; cp < 4; ++cp)
            hw[cp] = h2u(acc[r][cp * 2], acc[r][cp * 2 + 1]);
        *(uint4*)(g_Wh_h + (size_t)row * FO + fg * 8) = make_uint4(hw[0], hw[1], hw[2], hw[3]);
    }
}

// ---------------------------------------------------------------------------
// Kernel 2: fused GAT attention, fp16 mma.sync, K-split warps, 3-stage
// cp.async pipeline. P generated by fp16 bit-select (set.gt + LOP3), and the
// softmax denominator comes from a ones-column (col 64) through the MMA.
// ---------------------------------------------------------------------------
#define SB_STRIDE 144            // 72 fp16 cols: 64 data + col64=1.0 + zeros
#define SB_PLANE  (64 * SB_STRIDE)          // 9216
#define ADJ_STRIDE 272           // (64+4) ints, 16B aligned, bank-spread
#define ADJ_TILE  (64 * ADJ_STRIDE)         // 17408
#define NSTAGE 3
#define OFF_SB    16384                         // after 16KB scolp
#define OFF_ADJ   (OFF_SB + NSTAGE * SB_PLANE)  // 44032
#define GAT_SMEM  (OFF_ADJ + NSTAGE * ADJ_TILE) // 96256
#define ACC_STRIDE 76            // 9 blocks*8 + den + pad

__device__ __forceinline__ void stage_chunk(uint32_t swh, uint32_t sadj, int buf,
                                            int rowbase, const int* __restrict__ adjbase,
                                            int j0, int tid) {
    // Wh tile: 64 rows x 64 fp16 (8 KB), L1-cached (cross-CTA reuse)
    const uint32_t wbase = swh + buf * SB_PLANE;
    #pragma unroll
    for (int q = 0; q < 2; ++q) {
        const int id  = tid + q * 256;     // 0..511
        const int row = id >> 3;
        const int c16 = id & 7;
        const __half* src = g_Wh_h + (size_t)(rowbase + row) * FO + c16 * 8;
        cpasync16(wbase + row * SB_STRIDE + c16 * 16, src);
    }
    // adj tile: 64 rows x 64 int32 (16 KB), L1-bypass (single use chip-wide)
    const uint32_t abase = sadj + buf * ADJ_TILE;
    #pragma unroll
    for (int q = 0; q < 4; ++q) {
        const int id  = tid + q * 256;     // 0..1023
        const int row = id >> 4;
        const int c16 = id & 15;
        const int* src = adjbase + (size_t)row * NN + j0 + c16 * 4;
        cpasync16cg(abase + row * ADJ_STRIDE + c16 * 16, src);
    }
}

__global__ void __launch_bounds__(256, 2) gat_kernel(const int* __restrict__ adj,
                                                     float* __restrict__ out) {
    extern __shared__ __align__(16) unsigned char smem_raw[];
    uint4* scolp = (uint4*)smem_raw;                        // 16KB (per j-pair)
    float* accbuf = (float*)(smem_raw + OFF_SB);            // reuses staging
    const uint32_t swh  = smem_u32(smem_raw) + OFF_SB;
    const uint32_t sadj = smem_u32(smem_raw) + OFF_ADJ;

    const int tid  = threadIdx.x;
    const int lane = tid & 31;
    const int wid  = tid >> 5;
    const int b    = blockIdx.y;
    const int i0   = blockIdx.x * TI;

    const int mb    = (wid & 3) * 16;   // warp row base (local, 0..48)
    const int khalf = wid >> 2;         // 0: k-slices 0-1, 1: k-slices 2-3
    const int lrl = mb + (lane >> 2);   // local row (lo)
    const int lrh = lrl + 8;
    const int qc  = (lane & 3) * 2;     // k-pair base within 16

    // preload packed scol pairs for batch b (16KB)
    {
        const uint4* src = g_scolP + b * (NN / 2);
        #pragma unroll 2
        for (int i = tid; i < NN / 2; i += 256) scolp[i] = src[i];
    }
    // one-time init: pad cols 64-71 -> (1.0h, 0...) in all stage buffers
    for (int id = tid; id < NSTAGE * 64; id += 256) {
        const int s = id >> 6, row = id & 63;
        *(uint4*)(smem_raw + OFF_SB + s * SB_PLANE + row * SB_STRIDE + 128) =
            make_uint4(0x3C00u, 0u, 0u, 0u);
    }

    const uint4 rplo = g_srowP[b * NN + i0 + lrl];
    const uint4 rphi = g_srowP[b * NN + i0 + lrh];
    const int* adjbase = adj + ((size_t)b * NN + i0) * NN;

    stage_chunk(swh, sadj, 0, b * NN, adjbase, 0, tid);
    asm volatile("cp.async.commit_group;" ::: "memory");
    stage_chunk(swh, sadj, 1, b * NN + KT, adjbase, KT, tid);
    asm volatile("cp.async.commit_group;" ::: "memory");
    __syncthreads();   // scolp + pad init visible

    float acc[9][4];   // blocks 0-7: cols 0-63; block 8: den (col 64)
    #pragma unroll
    for (int nt = 0; nt < 9; ++nt)
        #pragma unroll
        for (int k = 0; k < 4; ++k) acc[nt][k] = 0.f;

    const int lrow = (lane & 7) + (lane & 8);       // ldmatrix x4 row 0..15
    const int lcol = (lane >> 4) << 3;              // 0 or 8
    const int drow = lane & 15;                     // ldmatrix x2 row

    #pragma unroll 1
    for (int t = 0; t < NCHUNK; ++t) {
        if (t + 2 < NCHUNK) {
            stage_chunk(swh, sadj, (t + 2) % NSTAGE, b * NN + (t + 2) * KT,
                        adjbase, (t + 2) * KT, tid);
            asm volatile("cp.async.commit_group;" ::: "memory");
            asm volatile("cp.async.wait_group 2;" ::: "memory");
        } else if (t + 1 < NCHUNK) {
            asm volatile("cp.async.wait_group 1;" ::: "memory");
        } else {
            asm volatile("cp.async.wait_group 0;" ::: "memory");
        }
        __syncthreads();   // chunk t landed everywhere

        const uint32_t bufh = swh  + (t % NSTAGE) * SB_PLANE;
        const uint32_t abuf = sadj + (t % NSTAGE) * ADJ_TILE;

        #pragma unroll
        for (int kt2 = 0; kt2 < 2; ++kt2) {
            const int ktg = khalf * 2 + kt2;          // this warp's k-slice
            const int jl  = ktg * 16 + qc;            // local j within chunk
            const int jp  = t * 32 + (jl >> 1);       // j-pair index
            const uint4 c01 = scolp[jp];
            const uint4 c89 = scolp[jp + 4];
            const uint32_t al_lo = abuf + lrl * ADJ_STRIDE + jl * 4;
            const uint32_t al_hi = abuf + lrh * ADJ_STRIDE + jl * 4;
            const int2 al0 = lds64(al_lo);
            const int2 al8 = lds64(al_lo + 32);
            const int2 ah0 = lds64(al_hi);
            const int2 ah8 = lds64(al_hi + 32);

            // A fragments: p = bitsel(E,F, s2>-s1) pairwise, masked by adj
            uint32_t m;
            m = setgt2(c01.x, rplo.x);
            const uint32_t a0 = hmul2u(bsel(rplo.y, rplo.z, m), bsel(c01.y, c01.z, m))
                                & adjmask(al0.x, al0.y);
            m = setgt2(c01.x, rphi.x);
            const uint32_t a1 = hmul2u(bsel(rphi.y, rphi.z, m), bsel(c01.y, c01.z, m))
                                & adjmask(ah0.x, ah0.y);
            m = setgt2(c89.x, rplo.x);
            const uint32_t a2 = hmul2u(bsel(rplo.y, rplo.z, m), bsel(c89.y, c89.z, m))
                                & adjmask(al8.x, al8.y);
            m = setgt2(c89.x, rphi.x);
            const uint32_t a3 = hmul2u(bsel(rphi.y, rphi.z, m), bsel(c89.y, c89.z, m))
                                & adjmask(ah8.x, ah8.y);

            // B fragments: 64 data cols + ones column (den)
            const uint32_t rowoff = (uint32_t)(ktg * 16 + lrow) * SB_STRIDE + lcol * 2;
            #pragma unroll
            for (int ci = 0; ci < 4; ++ci) {
                uint32_t bt[4];
                ldsm4t(bt, bufh + rowoff + ci * 32);
                mma16816(acc[ci * 2 + 0], a0, a1, a2, a3, bt[0], bt[1]);
                mma16816(acc[ci * 2 + 1], a0, a1, a2, a3, bt[2], bt[3]);
            }
            uint32_t dt[2];
            ldsm2t(dt, bufh + (uint32_t)(ktg * 16 + drow) * SB_STRIDE + 128);
            mma16816(acc[8], a0, a1, a2, a3, dt[0], dt[1]);
        }
        __syncthreads();   // all reads of buffers t done before re-staging
    }

    // ---- merge across khalf: khalf=1 publishes partials (staging is free)
    if (khalf) {
        #pragma unroll
        for (int nt = 0; nt < 8; ++nt) {
            *(float2*)(accbuf + lrl * ACC_STRIDE + nt * 8 + qc) =
                make_float2(acc[nt][0], acc[nt][1]);
            *(float2*)(accbuf + lrh * ACC_STRIDE + nt * 8 + qc) =
                make_float2(acc[nt][2], acc[nt][3]);
        }
        if ((lane & 3) == 0) {
            accbuf[lrl * ACC_STRIDE + 72] = acc[8][0];
            accbuf[lrh * ACC_STRIDE + 72] = acc[8][2];
        }
    }
    __syncthreads();

    if (!khalf) {
        float invl = 0.f, invh = 0.f;
        if ((lane & 3) == 0) {
            invl = 1.0f / (acc[8][0] + accbuf[lrl * ACC_STRIDE + 72]);
            invh = 1.0f / (acc[8][2] + accbuf[lrh * ACC_STRIDE + 72]);
        }
        invl = __shfl_sync(0xffffffffu, invl, lane & ~3);
        invh = __shfl_sync(0xffffffffu, invh, lane & ~3);
        float* outl = out + (size_t)(b * NN + i0 + lrl) * FO;
        float* outh = out + (size_t)(b * NN + i0 + lrh) * FO;
        #pragma unroll
        for (int nt = 0; nt < 8; ++nt) {
            const int cb = nt * 8 + qc;
            const float2 tl = *(const float2*)(accbuf + lrl * ACC_STRIDE + cb);
            const float2 th = *(const float2*)(accbuf + lrh * ACC_STRIDE + cb);
            float2 o;
            float v;
            v = (acc[nt][0] + tl.x) * invl; o.x = (v > 0.f) ? v : expm1f(v);
            v = (acc[nt][1] + tl.y) * invl; o.y = (v > 0.f) ? v : expm1f(v);
            *(float2*)(outl + cb) = o;
            v = (acc[nt][2] + th.x) * invh; o.x = (v > 0.f) ? v : expm1f(v);
            v = (acc[nt][3] + th.y) * invh; o.y = (v > 0.f) ? v : expm1f(v);
            *(float2*)(outh + cb) = o;
        }
    }
}

// ---------------------------------------------------------------------------
extern "C" void kernel_launch(void* const* d_in, const int* in_sizes, int n_in,
                              void* d_out, int out_size) {
    const float* h   = (const float*)d_in[0];   // [8,2048,128] f32
    const float* W   = (const float*)d_in[1];   // [128,64] f32
    const float* a   = (const float*)d_in[2];   // [128,1] f32
    const int*   adj = (const int*)d_in[3];     // [8,2048,2048] i32
    float* out = (float*)d_out;                 // [8,2048,64] f32

    cudaFuncSetAttribute(wh_kernel, cudaFuncAttributeMaxDynamicSharedMemorySize, 98304);
    cudaFuncSetAttribute(gat_kernel, cudaFuncAttributeMaxDynamicSharedMemorySize, GAT_SMEM);

    wh_kernel<<<BB * NN / 128, 256, 98304>>>(h, W, a);
    dim3 grid(NN / TI, BB);
    gat_kernel<<<grid, 256, GAT_SMEM>>>(adj, out);
}